// round 11
// baseline (speedup 1.0000x reference)
#include <cuda_runtime.h>
#include <cuda_bf16.h>
#include <math.h>

// Problem constants
#define NTOK 4096
#define CDIM 1024
#define NH   16
#define HD   64

typedef unsigned long long ull;

// ---- packed fp32x2 helpers (sm_100+/sm_103a; bit-exact 2x fp32 FMA) -------
__device__ __forceinline__ ull fma2(ull a, ull b, ull c) {
    ull d;
    asm("fma.rn.f32x2 %0, %1, %2, %3;" : "=l"(d) : "l"(a), "l"(b), "l"(c));
    return d;
}
__device__ __forceinline__ ull mul2(ull a, ull b) {
    ull d;
    asm("mul.rn.f32x2 %0, %1, %2;" : "=l"(d) : "l"(a), "l"(b));
    return d;
}
__device__ __forceinline__ ull bcast2(float x) {
    ull d; unsigned u = __float_as_uint(x);
    asm("mov.b64 %0, {%1, %1};" : "=l"(d) : "r"(u));
    return d;
}
__device__ __forceinline__ float2 unpack2(ull v) {
    unsigned lo, hi;
    asm("mov.b64 {%0, %1}, %2;" : "=r"(lo), "=r"(hi) : "l"(v));
    return make_float2(__uint_as_float(lo), __uint_as_float(hi));
}
__device__ __forceinline__ ull pack2(float lo, float hi) {
    ull d; unsigned a = __float_as_uint(lo), b = __float_as_uint(hi);
    asm("mov.b64 %0, {%1, %2};" : "=l"(d) : "r"(a), "r"(b));
    return d;
}

// qkv scratch: [N][3][H][HD] row-major = [4096][3072]
__device__ float g_qkv[NTOK * 3 * CDIM];
// attention output: [N][C]
__device__ float g_attn[NTOK * CDIM];

// ---------------------------------------------------------------------------
// SGEMM NT: C[M,N] = A[M,K] * B[N,K]^T.  128x128 block, BK=16, 256 threads,
// 8x8 per thread. Double-buffered smem + register prefetch. Inner product via
// packed f32x2 FMAs: i-pairs free from aligned smem loads, b broadcast-packed.
// ---------------------------------------------------------------------------
__global__ void __launch_bounds__(256) sgemm_nt(const float* __restrict__ A,
                                                const float* __restrict__ B,
                                                float* __restrict__ C,
                                                int M, int N, int K) {
    __shared__ __align__(16) float As[2][16][132];
    __shared__ __align__(16) float Bs[2][16][132];

    const int tid = threadIdx.x;
    const int tr  = tid >> 4;      // 0..15
    const int tc  = tid & 15;      // 0..15
    const int bm  = blockIdx.y << 7;
    const int bn  = blockIdx.x << 7;
    const int lr  = tid >> 2;          // 0..63
    const int lk  = (tid & 3) << 2;    // 0,4,8,12

    const float* Abase = A + (size_t)(bm + lr) * K + lk;
    const float* Bbase = B + (size_t)(bn + lr) * K + lk;
    const size_t rowK64 = (size_t)64 * K;

    // acc2[p][j] packs output rows (2p, 2p+1) of the thread's 8-row group
    ull acc2[4][8];
#pragma unroll
    for (int p = 0; p < 4; p++)
#pragma unroll
        for (int j = 0; j < 8; j++) acc2[p][j] = 0ull;

    float4 av0, av1, bv0, bv1;

    av0 = *reinterpret_cast<const float4*>(Abase);
    av1 = *reinterpret_cast<const float4*>(Abase + rowK64);
    bv0 = *reinterpret_cast<const float4*>(Bbase);
    bv1 = *reinterpret_cast<const float4*>(Bbase + rowK64);
    {
        As[0][lk + 0][lr] = av0.x; As[0][lk + 1][lr] = av0.y;
        As[0][lk + 2][lr] = av0.z; As[0][lk + 3][lr] = av0.w;
        As[0][lk + 0][64 + lr] = av1.x; As[0][lk + 1][64 + lr] = av1.y;
        As[0][lk + 2][64 + lr] = av1.z; As[0][lk + 3][64 + lr] = av1.w;
        Bs[0][lk + 0][lr] = bv0.x; Bs[0][lk + 1][lr] = bv0.y;
        Bs[0][lk + 2][lr] = bv0.z; Bs[0][lk + 3][lr] = bv0.w;
        Bs[0][lk + 0][64 + lr] = bv1.x; Bs[0][lk + 1][64 + lr] = bv1.y;
        Bs[0][lk + 2][64 + lr] = bv1.z; Bs[0][lk + 3][64 + lr] = bv1.w;
    }
    __syncthreads();

    int buf = 0;
    for (int k0 = 16; k0 <= K; k0 += 16) {
        const bool has_next = (k0 < K);
        if (has_next) {
            av0 = *reinterpret_cast<const float4*>(Abase + k0);
            av1 = *reinterpret_cast<const float4*>(Abase + k0 + rowK64);
            bv0 = *reinterpret_cast<const float4*>(Bbase + k0);
            bv1 = *reinterpret_cast<const float4*>(Bbase + k0 + rowK64);
        }

#pragma unroll
        for (int k = 0; k < 16; k++) {
            // a: 4 packed i-pairs, free from 16B-aligned smem loads
            ulonglong2 a01 = *reinterpret_cast<const ulonglong2*>(
                &As[buf][k][tr << 2]);
            ulonglong2 a23 = *reinterpret_cast<const ulonglong2*>(
                &As[buf][k][64 + (tr << 2)]);
            ull apair[4] = {a01.x, a01.y, a23.x, a23.y};

            float4 b0 = *reinterpret_cast<const float4*>(&Bs[buf][k][tc << 2]);
            float4 b1 = *reinterpret_cast<const float4*>(&Bs[buf][k][64 + (tc << 2)]);
            ull rbd[8];
            rbd[0] = bcast2(b0.x); rbd[1] = bcast2(b0.y);
            rbd[2] = bcast2(b0.z); rbd[3] = bcast2(b0.w);
            rbd[4] = bcast2(b1.x); rbd[5] = bcast2(b1.y);
            rbd[6] = bcast2(b1.z); rbd[7] = bcast2(b1.w);

#pragma unroll
            for (int p = 0; p < 4; p++)
#pragma unroll
                for (int j = 0; j < 8; j++)
                    acc2[p][j] = fma2(apair[p], rbd[j], acc2[p][j]);
        }

        if (has_next) {
            int nb = buf ^ 1;
            As[nb][lk + 0][lr] = av0.x; As[nb][lk + 1][lr] = av0.y;
            As[nb][lk + 2][lr] = av0.z; As[nb][lk + 3][lr] = av0.w;
            As[nb][lk + 0][64 + lr] = av1.x; As[nb][lk + 1][64 + lr] = av1.y;
            As[nb][lk + 2][64 + lr] = av1.z; As[nb][lk + 3][64 + lr] = av1.w;
            Bs[nb][lk + 0][lr] = bv0.x; Bs[nb][lk + 1][lr] = bv0.y;
            Bs[nb][lk + 2][lr] = bv0.z; Bs[nb][lk + 3][lr] = bv0.w;
            Bs[nb][lk + 0][64 + lr] = bv1.x; Bs[nb][lk + 1][64 + lr] = bv1.y;
            Bs[nb][lk + 2][64 + lr] = bv1.z; Bs[nb][lk + 3][64 + lr] = bv1.w;
            __syncthreads();
            buf = nb;
        }
    }

    // epilogue: unpack pairs -> rows
#pragma unroll
    for (int p = 0; p < 4; p++) {
#pragma unroll
        for (int half = 0; half < 2; half++) {
            int i = 2 * p + half;
            int row = bm + ((i < 4) ? ((tr << 2) + i) : (64 + (tr << 2) + i - 4));
            float* cp = C + (size_t)row * N + bn;
            float v[8];
#pragma unroll
            for (int j = 0; j < 8; j++) {
                float2 u = unpack2(acc2[p][j]);
                v[j] = half ? u.y : u.x;
            }
            *reinterpret_cast<float4*>(cp + (tc << 2)) =
                make_float4(v[0], v[1], v[2], v[3]);
            *reinterpret_cast<float4*>(cp + 64 + (tc << 2)) =
                make_float4(v[4], v[5], v[6], v[7]);
        }
    }
}

// ---------------------------------------------------------------------------
// Fused RMSNorm (q,k) + RoPE, in-place on g_qkv. One warp per (n, h).
// ---------------------------------------------------------------------------
__global__ void __launch_bounds__(256) rmsnorm_rope_kernel(
    const int* __restrict__ coords,
    const float* __restrict__ gq, const float* __restrict__ gk) {
    int gw   = (blockIdx.x * 256 + threadIdx.x) >> 5;
    int lane = threadIdx.x & 31;
    int n = gw >> 4;
    int h = gw & 15;

    float* qp = g_qkv + (size_t)n * 3072 + h * 64;
    float* kp = qp + 1024;

    float2 q = *reinterpret_cast<float2*>(qp + 2 * lane);
    float2 k = *reinterpret_cast<float2*>(kp + 2 * lane);

    float sq = q.x * q.x + q.y * q.y;
    float sk = k.x * k.x + k.y * k.y;
#pragma unroll
    for (int msk = 16; msk > 0; msk >>= 1) {
        sq += __shfl_xor_sync(0xffffffffu, sq, msk);
        sk += __shfl_xor_sync(0xffffffffu, sk, msk);
    }
    float invq = 8.0f / fmaxf(sqrtf(sq), 1e-12f);
    float invk = 8.0f / fmaxf(sqrtf(sk), 1e-12f);

    float2 gqv = *reinterpret_cast<const float2*>(gq + h * 64 + 2 * lane);
    float2 gkv = *reinterpret_cast<const float2*>(gk + h * 64 + 2 * lane);
    float q0 = q.x * invq * gqv.x, q1 = q.y * invq * gqv.y;
    float k0 = k.x * invk * gkv.x, k1 = k.y * invk * gkv.y;

    int p = lane >> 3, j = lane & 7;
    float freq = expf(-(float)j * (float)(9.210340371976184 / 64.0));
    float ang  = (float)coords[n * 5 + 1 + p] * freq;
    float sv, cv;
    sincosf(ang, &sv, &cv);

    float2 qo = make_float2(q0 * cv - q1 * sv, q0 * sv + q1 * cv);
    float2 ko = make_float2(k0 * cv - k1 * sv, k0 * sv + k1 * cv);
    *reinterpret_cast<float2*>(qp + 2 * lane) = qo;
    *reinterpret_cast<float2*>(kp + 2 * lane) = ko;
}

// ---------------------------------------------------------------------------
// Flash attention, fp32 math via packed f32x2 FMAs, double-buffered K/V.
// One block = 64 queries of one head; 256 threads; 4x4 tile per thread, with
// the 4 rows held as 2 packed row-pairs. Row stats reduced across the 16
// tc-threads of each row (16-lane half-warp shuffles).
// ---------------------------------------------------------------------------
#define APAD 68
#define TILE_F (64 * APAD)          // one 64x68 tile, in floats
#define ATTN_SMEM (6 * TILE_F * 4)

__global__ void __launch_bounds__(256, 2) attn_kernel() {
    extern __shared__ __align__(16) float sm[];
    float* Qs = sm;                  // [64][68]      (d-major: Qs[d][q])
    float* Ks0 = sm + TILE_F;        // [2][64][68]   (d-major), stride TILE_F
    float* Vs0 = sm + 3 * TILE_F;    // [2][64][68]   (k-major), stride TILE_F
    float* Ps = sm + 5 * TILE_F;     // [64][68]      (k-major: Ps[k][q])

    const int tid = threadIdx.x;
    const int tr  = tid >> 4;
    const int tc  = tid & 15;
    const int h   = blockIdx.y;
    const int q0  = blockIdx.x << 6;

    // Load Q tile transposed, pre-scaled by 1/sqrt(HD)
    for (int i = tid; i < 1024; i += 256) {
        int row = i >> 4;
        int d4  = (i & 15) << 2;
        float4 v = *reinterpret_cast<const float4*>(
            g_qkv + (size_t)(q0 + row) * 3072 + h * 64 + d4);
        Qs[(d4 + 0) * APAD + row] = v.x * 0.125f;
        Qs[(d4 + 1) * APAD + row] = v.y * 0.125f;
        Qs[(d4 + 2) * APAD + row] = v.z * 0.125f;
        Qs[(d4 + 3) * APAD + row] = v.w * 0.125f;
    }

    float m[4], l[4];
    ull o2[2][4];   // o2[p][j] packs rows (2p,2p+1), col j
#pragma unroll
    for (int i = 0; i < 4; i++) { m[i] = -1e30f; l[i] = 0.f; }
#pragma unroll
    for (int p = 0; p < 2; p++)
#pragma unroll
        for (int j = 0; j < 4; j++) o2[p][j] = 0ull;

    float4 kreg[4], vreg[4];

    // prologue: K/V tile 0 -> regs -> buffer 0
#pragma unroll
    for (int c = 0; c < 4; c++) {
        int i = tid + (c << 8);
        int row = i >> 4;
        int d4  = (i & 15) << 2;
        const float* p = g_qkv + (size_t)row * 3072 + 1024 + h * 64 + d4;
        kreg[c] = *reinterpret_cast<const float4*>(p);
        vreg[c] = *reinterpret_cast<const float4*>(p + 1024);
    }
#pragma unroll
    for (int c = 0; c < 4; c++) {
        int i = tid + (c << 8);
        int row = i >> 4;
        int d4  = (i & 15) << 2;
        Ks0[(d4 + 0) * APAD + row] = kreg[c].x;
        Ks0[(d4 + 1) * APAD + row] = kreg[c].y;
        Ks0[(d4 + 2) * APAD + row] = kreg[c].z;
        Ks0[(d4 + 3) * APAD + row] = kreg[c].w;
        *reinterpret_cast<float4*>(&Vs0[row * APAD + d4]) = vreg[c];
    }
    __syncthreads();

    int buf = 0;
    for (int t0 = 0; t0 < NTOK; t0 += 64) {
        const bool has_next = (t0 + 64 < NTOK);
        if (has_next) {
#pragma unroll
            for (int c = 0; c < 4; c++) {
                int i = tid + (c << 8);
                int row = i >> 4;
                int d4  = (i & 15) << 2;
                const float* p = g_qkv + (size_t)(t0 + 64 + row) * 3072
                                 + 1024 + h * 64 + d4;
                kreg[c] = *reinterpret_cast<const float4*>(p);
                vreg[c] = *reinterpret_cast<const float4*>(p + 1024);
            }
        }

        // buffer stride is ONE tile (TILE_F)
        const float* Ks = Ks0 + buf * TILE_F;
        const float* Vs = Vs0 + buf * TILE_F;

        // S = (Q*scale) . K^T  (2 row-pairs x 4 cols, packed)
        ull s2[2][4];
#pragma unroll
        for (int p = 0; p < 2; p++)
#pragma unroll
            for (int j = 0; j < 4; j++) s2[p][j] = 0ull;

#pragma unroll 16
        for (int d = 0; d < 64; d++) {
            ulonglong2 qa = *reinterpret_cast<const ulonglong2*>(
                &Qs[d * APAD + (tr << 2)]);
            float4 b = *reinterpret_cast<const float4*>(
                &Ks[d * APAD + (tc << 2)]);
            ull b0 = bcast2(b.x), b1 = bcast2(b.y);
            ull b2 = bcast2(b.z), b3 = bcast2(b.w);
            s2[0][0] = fma2(qa.x, b0, s2[0][0]);
            s2[0][1] = fma2(qa.x, b1, s2[0][1]);
            s2[0][2] = fma2(qa.x, b2, s2[0][2]);
            s2[0][3] = fma2(qa.x, b3, s2[0][3]);
            s2[1][0] = fma2(qa.y, b0, s2[1][0]);
            s2[1][1] = fma2(qa.y, b1, s2[1][1]);
            s2[1][2] = fma2(qa.y, b2, s2[1][2]);
            s2[1][3] = fma2(qa.y, b3, s2[1][3]);
        }

        // unpack to scalar for softmax
        float s[4][4];
#pragma unroll
        for (int p = 0; p < 2; p++)
#pragma unroll
            for (int j = 0; j < 4; j++) {
                float2 u = unpack2(s2[p][j]);
                s[2 * p][j] = u.x;
                s[2 * p + 1][j] = u.y;
            }

        // Online softmax (row stats across the row's 16 tc-threads)
        float corr[4];
#pragma unroll
        for (int i = 0; i < 4; i++) {
            float rm = fmaxf(fmaxf(s[i][0], s[i][1]), fmaxf(s[i][2], s[i][3]));
#pragma unroll
            for (int msk = 8; msk > 0; msk >>= 1)
                rm = fmaxf(rm, __shfl_xor_sync(0xffffffffu, rm, msk));
            float mn   = fmaxf(m[i], rm);
            corr[i] = __expf(m[i] - mn);
            float rs = 0.f;
#pragma unroll
            for (int j = 0; j < 4; j++) {
                s[i][j] = __expf(s[i][j] - mn);
                rs += s[i][j];
            }
#pragma unroll
            for (int msk = 8; msk > 0; msk >>= 1)
                rs += __shfl_xor_sync(0xffffffffu, rs, msk);
            l[i] = l[i] * corr[i] + rs;
            m[i] = mn;
        }
        // rescale packed O accumulators by packed corr pairs
        ull c0 = pack2(corr[0], corr[1]);
        ull c1 = pack2(corr[2], corr[3]);
#pragma unroll
        for (int j = 0; j < 4; j++) {
            o2[0][j] = mul2(o2[0][j], c0);
            o2[1][j] = mul2(o2[1][j], c1);
        }

        // Store P transposed: Ps[k][q]
#pragma unroll
        for (int i = 0; i < 4; i++)
#pragma unroll
            for (int j = 0; j < 4; j++)
                Ps[((tc << 2) + j) * APAD + (tr << 2) + i] = s[i][j];
        __syncthreads();

        // O += P . V  (packed over the 4 query rows)
#pragma unroll 16
        for (int k = 0; k < 64; k++) {
            ulonglong2 pa = *reinterpret_cast<const ulonglong2*>(
                &Ps[k * APAD + (tr << 2)]);
            float4 b = *reinterpret_cast<const float4*>(
                &Vs[k * APAD + (tc << 2)]);
            ull b0 = bcast2(b.x), b1 = bcast2(b.y);
            ull b2 = bcast2(b.z), b3 = bcast2(b.w);
            o2[0][0] = fma2(pa.x, b0, o2[0][0]);
            o2[0][1] = fma2(pa.x, b1, o2[0][1]);
            o2[0][2] = fma2(pa.x, b2, o2[0][2]);
            o2[0][3] = fma2(pa.x, b3, o2[0][3]);
            o2[1][0] = fma2(pa.y, b0, o2[1][0]);
            o2[1][1] = fma2(pa.y, b1, o2[1][1]);
            o2[1][2] = fma2(pa.y, b2, o2[1][2]);
            o2[1][3] = fma2(pa.y, b3, o2[1][3]);
        }

        if (has_next) {
            // one-tile stride here too
            float* Kn = Ks0 + (buf ^ 1) * TILE_F;
            float* Vn = Vs0 + (buf ^ 1) * TILE_F;
#pragma unroll
            for (int c = 0; c < 4; c++) {
                int i = tid + (c << 8);
                int row = i >> 4;
                int d4  = (i & 15) << 2;
                Kn[(d4 + 0) * APAD + row] = kreg[c].x;
                Kn[(d4 + 1) * APAD + row] = kreg[c].y;
                Kn[(d4 + 2) * APAD + row] = kreg[c].z;
                Kn[(d4 + 3) * APAD + row] = kreg[c].w;
                *reinterpret_cast<float4*>(&Vn[row * APAD + d4]) = vreg[c];
            }
        }
        __syncthreads();
        buf ^= 1;
    }

    // Finalize: unpack O pairs, normalize, store
#pragma unroll
    for (int p = 0; p < 2; p++) {
        float inv0 = 1.0f / l[2 * p];
        float inv1 = 1.0f / l[2 * p + 1];
        float v0[4], v1[4];
#pragma unroll
        for (int j = 0; j < 4; j++) {
            float2 u = unpack2(o2[p][j]);
            v0[j] = u.x * inv0;
            v1[j] = u.y * inv1;
        }
        int row0 = q0 + (tr << 2) + 2 * p;
        *reinterpret_cast<float4*>(
            g_attn + (size_t)row0 * CDIM + h * 64 + (tc << 2)) =
            make_float4(v0[0], v0[1], v0[2], v0[3]);
        *reinterpret_cast<float4*>(
            g_attn + (size_t)(row0 + 1) * CDIM + h * 64 + (tc << 2)) =
            make_float4(v1[0], v1[1], v1[2], v1[3]);
    }
}

// ---------------------------------------------------------------------------
extern "C" void kernel_launch(void* const* d_in, const int* in_sizes, int n_in,
                              void* d_out, int out_size) {
    const float* x      = (const float*)d_in[0];
    const int*   coords = (const int*)d_in[1];
    const float* w_qkv  = (const float*)d_in[2];
    const float* w_out  = (const float*)d_in[3];
    const float* gq     = (const float*)d_in[4];
    const float* gk     = (const float*)d_in[5];
    float* out = (float*)d_out;

    float *qkv, *attn;
    cudaGetSymbolAddress((void**)&qkv,  g_qkv);
    cudaGetSymbolAddress((void**)&attn, g_attn);
    cudaFuncSetAttribute(attn_kernel,
                         cudaFuncAttributeMaxDynamicSharedMemorySize, ATTN_SMEM);

    // 1. qkv = x @ w_qkv^T   [4096,3072]
    sgemm_nt<<<dim3(3 * CDIM / 128, NTOK / 128), 256>>>(
        x, w_qkv, qkv, NTOK, 3 * CDIM, CDIM);

    // 2. rmsnorm + rope on q,k (in place)
    rmsnorm_rope_kernel<<<NTOK * NH / 8, 256>>>(coords, gq, gk);

    // 3. attention per head -> g_attn [4096,1024]
    attn_kernel<<<dim3(NTOK / 64, NH), 256, ATTN_SMEM>>>();

    // 4. out = attn @ w_out^T  [4096,1024]
    sgemm_nt<<<dim3(CDIM / 128, NTOK / 128), 256>>>(
        attn, w_out, out, NTOK, CDIM, CDIM);
}

// round 16
// speedup vs baseline: 1.5821x; 1.5821x over previous
#include <cuda_runtime.h>
#include <cuda_bf16.h>
#include <math.h>
#include <stdint.h>

// Problem constants
#define NTOK 4096
#define CDIM 1024
#define NH   16
#define HD   64

typedef unsigned long long ull;

// ---- packed fp32x2 helpers (bit-exact 2x fp32 FMA) ------------------------
__device__ __forceinline__ ull fma2(ull a, ull b, ull c) {
    ull d;
    asm("fma.rn.f32x2 %0, %1, %2, %3;" : "=l"(d) : "l"(a), "l"(b), "l"(c));
    return d;
}
__device__ __forceinline__ ull bcast2(float x) {
    ull d; unsigned u = __float_as_uint(x);
    asm("mov.b64 %0, {%1, %1};" : "=l"(d) : "r"(u));
    return d;
}
__device__ __forceinline__ float2 unpack2(ull v) {
    unsigned lo, hi;
    asm("mov.b64 {%0, %1}, %2;" : "=r"(lo), "=r"(hi) : "l"(v));
    return make_float2(__uint_as_float(lo), __uint_as_float(hi));
}

__device__ __forceinline__ uint32_t smem_u32(const void* p) {
    uint32_t a;
    asm("{ .reg .u64 t; cvta.to.shared.u64 t, %1; cvt.u32.u64 %0, t; }"
        : "=r"(a) : "l"(p));
    return a;
}
__device__ __forceinline__ uint32_t pack_bf16(__nv_bfloat16 lo, __nv_bfloat16 hi) {
    return (uint32_t)__bfloat16_as_ushort(lo) |
           ((uint32_t)__bfloat16_as_ushort(hi) << 16);
}
// pack hi/lo bf16 decomposition of two floats
__device__ __forceinline__ void hilo2(float x, float y, uint32_t& hi, uint32_t& lo) {
    __nv_bfloat16 bx = __float2bfloat16(x);
    __nv_bfloat16 by = __float2bfloat16(y);
    hi = pack_bf16(bx, by);
    lo = pack_bf16(__float2bfloat16(x - __bfloat162float(bx)),
                   __float2bfloat16(y - __bfloat162float(by)));
}

#define MMA_BF16(c0, c1, c2, c3, a0, a1, a2, a3, b0, b1) \
    asm volatile("mma.sync.aligned.m16n8k16.row.col.f32.bf16.bf16.f32 " \
        "{%0,%1,%2,%3}, {%4,%5,%6,%7}, {%8,%9}, {%0,%1,%2,%3};" \
        : "+f"(c0), "+f"(c1), "+f"(c2), "+f"(c3) \
        : "r"(a0), "r"(a1), "r"(a2), "r"(a3), "r"(b0), "r"(b1))

#define LDSM_X2(r0, r1, addr) \
    asm volatile("ldmatrix.sync.aligned.m8n8.x2.shared.b16 {%0,%1}, [%2];" \
                 : "=r"(r0), "=r"(r1) : "r"(addr))
#define LDSM_X2T(r0, r1, addr) \
    asm volatile("ldmatrix.sync.aligned.m8n8.x2.trans.shared.b16 {%0,%1}, [%2];" \
                 : "=r"(r0), "=r"(r1) : "r"(addr))

// qkv scratch: [N][3][H][HD] row-major = [4096][3072]
__device__ float g_qkv[NTOK * 3 * CDIM];
// attention output: [N][C]
__device__ float g_attn[NTOK * CDIM];

// ---------------------------------------------------------------------------
// SGEMM NT (fp32 f32x2) — unchanged from verified round-11 kernel
// ---------------------------------------------------------------------------
__global__ void __launch_bounds__(256) sgemm_nt(const float* __restrict__ A,
                                                const float* __restrict__ B,
                                                float* __restrict__ C,
                                                int M, int N, int K) {
    __shared__ __align__(16) float As[2][16][132];
    __shared__ __align__(16) float Bs[2][16][132];

    const int tid = threadIdx.x;
    const int tr  = tid >> 4;
    const int tc  = tid & 15;
    const int bm  = blockIdx.y << 7;
    const int bn  = blockIdx.x << 7;
    const int lr  = tid >> 2;
    const int lk  = (tid & 3) << 2;

    const float* Abase = A + (size_t)(bm + lr) * K + lk;
    const float* Bbase = B + (size_t)(bn + lr) * K + lk;
    const size_t rowK64 = (size_t)64 * K;

    ull acc2[4][8];
#pragma unroll
    for (int p = 0; p < 4; p++)
#pragma unroll
        for (int j = 0; j < 8; j++) acc2[p][j] = 0ull;

    float4 av0, av1, bv0, bv1;
    av0 = *reinterpret_cast<const float4*>(Abase);
    av1 = *reinterpret_cast<const float4*>(Abase + rowK64);
    bv0 = *reinterpret_cast<const float4*>(Bbase);
    bv1 = *reinterpret_cast<const float4*>(Bbase + rowK64);
    {
        As[0][lk + 0][lr] = av0.x; As[0][lk + 1][lr] = av0.y;
        As[0][lk + 2][lr] = av0.z; As[0][lk + 3][lr] = av0.w;
        As[0][lk + 0][64 + lr] = av1.x; As[0][lk + 1][64 + lr] = av1.y;
        As[0][lk + 2][64 + lr] = av1.z; As[0][lk + 3][64 + lr] = av1.w;
        Bs[0][lk + 0][lr] = bv0.x; Bs[0][lk + 1][lr] = bv0.y;
        Bs[0][lk + 2][lr] = bv0.z; Bs[0][lk + 3][lr] = bv0.w;
        Bs[0][lk + 0][64 + lr] = bv1.x; Bs[0][lk + 1][64 + lr] = bv1.y;
        Bs[0][lk + 2][64 + lr] = bv1.z; Bs[0][lk + 3][64 + lr] = bv1.w;
    }
    __syncthreads();

    int buf = 0;
    for (int k0 = 16; k0 <= K; k0 += 16) {
        const bool has_next = (k0 < K);
        if (has_next) {
            av0 = *reinterpret_cast<const float4*>(Abase + k0);
            av1 = *reinterpret_cast<const float4*>(Abase + k0 + rowK64);
            bv0 = *reinterpret_cast<const float4*>(Bbase + k0);
            bv1 = *reinterpret_cast<const float4*>(Bbase + k0 + rowK64);
        }
#pragma unroll
        for (int k = 0; k < 16; k++) {
            ulonglong2 a01 = *reinterpret_cast<const ulonglong2*>(&As[buf][k][tr << 2]);
            ulonglong2 a23 = *reinterpret_cast<const ulonglong2*>(&As[buf][k][64 + (tr << 2)]);
            ull apair[4] = {a01.x, a01.y, a23.x, a23.y};
            float4 b0 = *reinterpret_cast<const float4*>(&Bs[buf][k][tc << 2]);
            float4 b1 = *reinterpret_cast<const float4*>(&Bs[buf][k][64 + (tc << 2)]);
            ull rbd[8];
            rbd[0] = bcast2(b0.x); rbd[1] = bcast2(b0.y);
            rbd[2] = bcast2(b0.z); rbd[3] = bcast2(b0.w);
            rbd[4] = bcast2(b1.x); rbd[5] = bcast2(b1.y);
            rbd[6] = bcast2(b1.z); rbd[7] = bcast2(b1.w);
#pragma unroll
            for (int p = 0; p < 4; p++)
#pragma unroll
                for (int j = 0; j < 8; j++)
                    acc2[p][j] = fma2(apair[p], rbd[j], acc2[p][j]);
        }
        if (has_next) {
            int nb = buf ^ 1;
            As[nb][lk + 0][lr] = av0.x; As[nb][lk + 1][lr] = av0.y;
            As[nb][lk + 2][lr] = av0.z; As[nb][lk + 3][lr] = av0.w;
            As[nb][lk + 0][64 + lr] = av1.x; As[nb][lk + 1][64 + lr] = av1.y;
            As[nb][lk + 2][64 + lr] = av1.z; As[nb][lk + 3][64 + lr] = av1.w;
            Bs[nb][lk + 0][lr] = bv0.x; Bs[nb][lk + 1][lr] = bv0.y;
            Bs[nb][lk + 2][lr] = bv0.z; Bs[nb][lk + 3][lr] = bv0.w;
            Bs[nb][lk + 0][64 + lr] = bv1.x; Bs[nb][lk + 1][64 + lr] = bv1.y;
            Bs[nb][lk + 2][64 + lr] = bv1.z; Bs[nb][lk + 3][64 + lr] = bv1.w;
            __syncthreads();
            buf = nb;
        }
    }
#pragma unroll
    for (int p = 0; p < 4; p++) {
#pragma unroll
        for (int half = 0; half < 2; half++) {
            int i = 2 * p + half;
            int row = bm + ((i < 4) ? ((tr << 2) + i) : (64 + (tr << 2) + i - 4));
            float* cp = C + (size_t)row * N + bn;
            float v[8];
#pragma unroll
            for (int j = 0; j < 8; j++) {
                float2 u = unpack2(acc2[p][j]);
                v[j] = half ? u.y : u.x;
            }
            *reinterpret_cast<float4*>(cp + (tc << 2)) =
                make_float4(v[0], v[1], v[2], v[3]);
            *reinterpret_cast<float4*>(cp + 64 + (tc << 2)) =
                make_float4(v[4], v[5], v[6], v[7]);
        }
    }
}

// ---------------------------------------------------------------------------
// Fused RMSNorm (q,k) + RoPE — unchanged (verified)
// ---------------------------------------------------------------------------
__global__ void __launch_bounds__(256) rmsnorm_rope_kernel(
    const int* __restrict__ coords,
    const float* __restrict__ gq, const float* __restrict__ gk) {
    int gw   = (blockIdx.x * 256 + threadIdx.x) >> 5;
    int lane = threadIdx.x & 31;
    int n = gw >> 4;
    int h = gw & 15;

    float* qp = g_qkv + (size_t)n * 3072 + h * 64;
    float* kp = qp + 1024;

    float2 q = *reinterpret_cast<float2*>(qp + 2 * lane);
    float2 k = *reinterpret_cast<float2*>(kp + 2 * lane);

    float sq = q.x * q.x + q.y * q.y;
    float sk = k.x * k.x + k.y * k.y;
#pragma unroll
    for (int msk = 16; msk > 0; msk >>= 1) {
        sq += __shfl_xor_sync(0xffffffffu, sq, msk);
        sk += __shfl_xor_sync(0xffffffffu, sk, msk);
    }
    float invq = 8.0f / fmaxf(sqrtf(sq), 1e-12f);
    float invk = 8.0f / fmaxf(sqrtf(sk), 1e-12f);

    float2 gqv = *reinterpret_cast<const float2*>(gq + h * 64 + 2 * lane);
    float2 gkv = *reinterpret_cast<const float2*>(gk + h * 64 + 2 * lane);
    float q0 = q.x * invq * gqv.x, q1 = q.y * invq * gqv.y;
    float k0 = k.x * invk * gkv.x, k1 = k.y * invk * gkv.y;

    int p = lane >> 3, j = lane & 7;
    float freq = expf(-(float)j * (float)(9.210340371976184 / 64.0));
    float ang  = (float)coords[n * 5 + 1 + p] * freq;
    float sv, cv;
    sincosf(ang, &sv, &cv);

    float2 qo = make_float2(q0 * cv - q1 * sv, q0 * sv + q1 * cv);
    float2 ko = make_float2(k0 * cv - k1 * sv, k0 * sv + k1 * cv);
    *reinterpret_cast<float2*>(qp + 2 * lane) = qo;
    *reinterpret_cast<float2*>(kp + 2 * lane) = ko;
}

// ---------------------------------------------------------------------------
// mma.sync bf16 flash attention, fixed-max softmax, FULL hi/lo error
// compensation on BOTH matmuls:
//   S = Qh.Kh + Ql.Kh + Qh.Kl      (round-13 fix: scores were raw bf16)
//   O = Ph.Vh + Pl.Vh + Ph.Vl
// Dropped cross terms (Ql.Kl, Pl.Vl) are O(2^-18) — negligible.
// Fixed max: rms-norm gives ||q/8||=1, ||k||=8 => s in [-8,8]; exp(s-8),
// no running max, O accumulates in fp32 C-fragments across all 64 tiles.
// Block = 64 queries x 1 head, 4 warps x 16 query rows.
// ---------------------------------------------------------------------------
#define KPAD 72   // row stride in bf16: 144B = 9*16 (ldmatrix-aligned, conflict-free)

__global__ void __launch_bounds__(128) attn3_kernel() {
    __shared__ __align__(16) __nv_bfloat16 Kh[64][KPAD];
    __shared__ __align__(16) __nv_bfloat16 Kl[64][KPAD];
    __shared__ __align__(16) __nv_bfloat16 Vh[64][KPAD];
    __shared__ __align__(16) __nv_bfloat16 Vl[64][KPAD];

    const int tid  = threadIdx.x;
    const int lane = tid & 31;
    const int warp = tid >> 5;
    const int g    = lane >> 2;   // fragment row group 0..7
    const int c    = lane & 3;    // fragment col group 0..3
    const int h    = blockIdx.y;
    const int qbase = blockIdx.x * 64 + warp * 16;

    // Q A-fragments (scaled by 1/8), hi + lo, loaded once.
    uint32_t aqh[4][4], aql[4][4];
    {
        const float* q0 = g_qkv + (size_t)(qbase + g) * 3072 + h * 64;
        const float* q8 = q0 + (size_t)8 * 3072;
#pragma unroll
        for (int j = 0; j < 4; j++) {
            float2 v;
            v = *reinterpret_cast<const float2*>(q0 + 16 * j + 2 * c);
            hilo2(v.x * 0.125f, v.y * 0.125f, aqh[j][0], aql[j][0]);
            v = *reinterpret_cast<const float2*>(q8 + 16 * j + 2 * c);
            hilo2(v.x * 0.125f, v.y * 0.125f, aqh[j][1], aql[j][1]);
            v = *reinterpret_cast<const float2*>(q0 + 16 * j + 2 * c + 8);
            hilo2(v.x * 0.125f, v.y * 0.125f, aqh[j][2], aql[j][2]);
            v = *reinterpret_cast<const float2*>(q8 + 16 * j + 2 * c + 8);
            hilo2(v.x * 0.125f, v.y * 0.125f, aqh[j][3], aql[j][3]);
        }
    }

    float o[8][4];
#pragma unroll
    for (int d = 0; d < 8; d++) {
        o[d][0] = 0.f; o[d][1] = 0.f; o[d][2] = 0.f; o[d][3] = 0.f;
    }
    float lsum0 = 0.f, lsum1 = 0.f;

    const uint32_t skh = smem_u32(&Kh[0][0]);
    const uint32_t skl = smem_u32(&Kl[0][0]);
    const uint32_t svh = smem_u32(&Vh[0][0]);
    const uint32_t svl = smem_u32(&Vl[0][0]);
    const int lm = lane & 15;   // ldmatrix address lane (x2 uses lanes 0..15)

    for (int t = 0; t < 64; t++) {
        // ---- load K hi/lo and V hi/lo tiles [key][dim] ----
        {
            const int r     = tid >> 1;
            const int dbase = (tid & 1) << 5;
            const float* kp = g_qkv + (size_t)(t * 64 + r) * 3072 + 1024 + h * 64 + dbase;
            const float* vp = kp + 1024;
#pragma unroll
            for (int i = 0; i < 8; i++) {
                float4 kv = *reinterpret_cast<const float4*>(kp + 4 * i);
                uint32_t kh0, kl0, kh1, kl1;
                hilo2(kv.x, kv.y, kh0, kl0);
                hilo2(kv.z, kv.w, kh1, kl1);
                uint32_t* dkh = reinterpret_cast<uint32_t*>(&Kh[r][dbase + 4 * i]);
                dkh[0] = kh0; dkh[1] = kh1;
                uint32_t* dkl = reinterpret_cast<uint32_t*>(&Kl[r][dbase + 4 * i]);
                dkl[0] = kl0; dkl[1] = kl1;

                float4 vv = *reinterpret_cast<const float4*>(vp + 4 * i);
                uint32_t vh0, vl0, vh1, vl1;
                hilo2(vv.x, vv.y, vh0, vl0);
                hilo2(vv.z, vv.w, vh1, vl1);
                uint32_t* dvh = reinterpret_cast<uint32_t*>(&Vh[r][dbase + 4 * i]);
                dvh[0] = vh0; dvh[1] = vh1;
                uint32_t* dvl = reinterpret_cast<uint32_t*>(&Vl[r][dbase + 4 * i]);
                dvl[0] = vl0; dvl[1] = vl1;
            }
        }
        __syncthreads();

        // ---- S = Qh.Kh + Ql.Kh + Qh.Kl : K[key][dim] is col-major B ----
        float e[8][4];
#pragma unroll
        for (int n = 0; n < 8; n++) { e[n][0] = e[n][1] = e[n][2] = e[n][3] = 0.f; }
#pragma unroll
        for (int j = 0; j < 4; j++) {
#pragma unroll
            for (int n = 0; n < 8; n++) {
                uint32_t off = (uint32_t)(((8 * n + (lm & 7)) * KPAD
                                 + 16 * j + ((lm >> 3) << 3)) * 2);
                uint32_t bh0, bh1, bl0, bl1;
                LDSM_X2(bh0, bh1, skh + off);
                LDSM_X2(bl0, bl1, skl + off);
                MMA_BF16(e[n][0], e[n][1], e[n][2], e[n][3],
                         aqh[j][0], aqh[j][1], aqh[j][2], aqh[j][3], bh0, bh1);
                MMA_BF16(e[n][0], e[n][1], e[n][2], e[n][3],
                         aql[j][0], aql[j][1], aql[j][2], aql[j][3], bh0, bh1);
                MMA_BF16(e[n][0], e[n][1], e[n][2], e[n][3],
                         aqh[j][0], aqh[j][1], aqh[j][2], aqh[j][3], bl0, bl1);
            }
        }

        // ---- softmax weights, fixed max 8; P hi/lo A-fragments ----
        uint32_t phi[4][4], plo[4][4];
#pragma unroll
        for (int n = 0; n < 8; n++) {
            float e0 = __expf(e[n][0] - 8.f);
            float e1 = __expf(e[n][1] - 8.f);
            float e2 = __expf(e[n][2] - 8.f);
            float e3 = __expf(e[n][3] - 8.f);
            lsum0 += e0 + e1;
            lsum1 += e2 + e3;
            int j = n >> 1, hh = (n & 1) << 1;
            hilo2(e0, e1, phi[j][hh],     plo[j][hh]);
            hilo2(e2, e3, phi[j][hh + 1], plo[j][hh + 1]);
        }

        // ---- O += Ph.Vh + Pl.Vh + Ph.Vl  (V via ldmatrix.trans) ----
#pragma unroll
        for (int j = 0; j < 4; j++) {
#pragma unroll
            for (int d = 0; d < 8; d++) {
                uint32_t rowoff = (uint32_t)(((16 * j + lm) * KPAD + 8 * d) * 2);
                uint32_t bh0, bh1, bl0, bl1;
                LDSM_X2T(bh0, bh1, svh + rowoff);
                LDSM_X2T(bl0, bl1, svl + rowoff);
                MMA_BF16(o[d][0], o[d][1], o[d][2], o[d][3],
                         phi[j][0], phi[j][1], phi[j][2], phi[j][3], bh0, bh1);
                MMA_BF16(o[d][0], o[d][1], o[d][2], o[d][3],
                         plo[j][0], plo[j][1], plo[j][2], plo[j][3], bh0, bh1);
                MMA_BF16(o[d][0], o[d][1], o[d][2], o[d][3],
                         phi[j][0], phi[j][1], phi[j][2], phi[j][3], bl0, bl1);
            }
        }
        __syncthreads();
    }

    // ---- finalize: row-sum reduce over the 4 threads sharing each row ----
    lsum0 += __shfl_xor_sync(0xffffffffu, lsum0, 1);
    lsum0 += __shfl_xor_sync(0xffffffffu, lsum0, 2);
    lsum1 += __shfl_xor_sync(0xffffffffu, lsum1, 1);
    lsum1 += __shfl_xor_sync(0xffffffffu, lsum1, 2);
    float inv0 = 1.0f / lsum0;
    float inv1 = 1.0f / lsum1;

    float* op0 = g_attn + (size_t)(qbase + g) * CDIM + h * 64;
    float* op8 = op0 + (size_t)8 * CDIM;
#pragma unroll
    for (int d = 0; d < 8; d++) {
        *reinterpret_cast<float2*>(op0 + 8 * d + 2 * c) =
            make_float2(o[d][0] * inv0, o[d][1] * inv0);
        *reinterpret_cast<float2*>(op8 + 8 * d + 2 * c) =
            make_float2(o[d][2] * inv1, o[d][3] * inv1);
    }
}

// ---------------------------------------------------------------------------
extern "C" void kernel_launch(void* const* d_in, const int* in_sizes, int n_in,
                              void* d_out, int out_size) {
    const float* x      = (const float*)d_in[0];
    const int*   coords = (const int*)d_in[1];
    const float* w_qkv  = (const float*)d_in[2];
    const float* w_out  = (const float*)d_in[3];
    const float* gq     = (const float*)d_in[4];
    const float* gk     = (const float*)d_in[5];
    float* out = (float*)d_out;

    float *qkv, *attn;
    cudaGetSymbolAddress((void**)&qkv,  g_qkv);
    cudaGetSymbolAddress((void**)&attn, g_attn);

    // 1. qkv = x @ w_qkv^T   [4096,3072]
    sgemm_nt<<<dim3(3 * CDIM / 128, NTOK / 128), 256>>>(
        x, w_qkv, qkv, NTOK, 3 * CDIM, CDIM);

    // 2. rmsnorm + rope on q,k (in place)
    rmsnorm_rope_kernel<<<NTOK * NH / 8, 256>>>(coords, gq, gk);

    // 3. mma.sync bf16 attention (full hi/lo compensation) -> g_attn
    attn3_kernel<<<dim3(NTOK / 64, NH), 128>>>();

    // 4. out = attn @ w_out^T  [4096,1024]
    sgemm_nt<<<dim3(CDIM / 128, NTOK / 128), 256>>>(
        attn, w_out, out, NTOK, CDIM, CDIM);
}